// round 12
// baseline (speedup 1.0000x reference)
#include <cuda_runtime.h>
#include <cuda_fp16.h>
#include <cstdint>

// Problem constants
#define Bn   2
#define Cc   320
#define Hh   128
#define Ww   256
#define Gg   40
#define CPG  8
#define Dd   48
#define XC   64
#define HW   (Hh*Ww)

// Merged scratch: half2 channel pairs. [n][mpair(128)][row(130)][col(264)] u32
#define MPAIR  128
#define MROWS  130
#define MSTR   264
#define MPSZ   (MROWS*MSTR)
#define MUTOT  ((size_t)Bn*MPAIR*MPSZ)

__device__ uint32_t g_mu[MUTOT];
__device__ uint32_t g_fwrh[16*72*64];   // packed half2 weights [chunk][kp(72)][o^sw(64)]

// ---------------------------------------------------------------------------
// helpers
// ---------------------------------------------------------------------------
__device__ __forceinline__ uint32_t pack2h(float a, float b) {
    __half2 h = __halves2half2(__float2half_rn(a), __float2half_rn(b));
    return *reinterpret_cast<uint32_t*>(&h);
}
__device__ __forceinline__ uint32_t smem_u32(const void* p) {
    uint32_t a;
    asm("{ .reg .u64 t; cvta.to.shared.u64 t, %1; cvt.u32.u64 %0, t; }" : "=r"(a) : "l"(p));
    return a;
}
__device__ __forceinline__ void cpasync16(uint32_t dst, const void* src) {
    asm volatile("cp.async.cg.shared.global [%0], [%1], 16;" :: "r"(dst), "l"(src) : "memory");
}
#define CP_COMMIT() asm volatile("cp.async.commit_group;" ::: "memory")
#define CP_WAIT(N)  asm volatile("cp.async.wait_group %0;" :: "n"(N) : "memory")

__device__ __forceinline__ void mma_f16(float* c, const uint32_t* a,
                                        uint32_t b0, uint32_t b1) {
    asm volatile("mma.sync.aligned.m16n8k16.row.col.f32.f16.f16.f32 "
        "{%0,%1,%2,%3}, {%4,%5,%6,%7}, {%8,%9}, {%0,%1,%2,%3};"
        : "+f"(c[0]), "+f"(c[1]), "+f"(c[2]), "+f"(c[3])
        : "r"(a[0]), "r"(a[1]), "r"(a[2]), "r"(a[3]), "r"(b0), "r"(b1));
}

// ---------------------------------------------------------------------------
// Kernel 1: groupwise-correlation cost volume (exact fp32).
// ---------------------------------------------------------------------------
__global__ void __launch_bounds__(256) gwc_kernel(const float* __restrict__ ref,
                                                  const float* __restrict__ tgt,
                                                  float* __restrict__ vol) {
    __shared__ __align__(16) float st[CPG][4][308];
    const int h0  = blockIdx.x * 4;
    const int g   = blockIdx.y;
    const int b   = blockIdx.z;
    const int tid = threadIdx.x;

    for (int q = tid; q < CPG*4*308; q += 256)
        (&st[0][0][0])[q] = 0.0f;
    __syncthreads();

    const int cbase = b*Cc + g*CPG;
    for (int q = tid; q < CPG*4*Ww; q += 256) {
        int w  = q & 255;
        int hr = (q >> 8) & 3;
        int c  = q >> 10;
        st[c][hr][51 + w] = __ldcs(&tgt[(size_t)((cbase + c)*Hh + h0 + hr)*Ww + w]);
    }
    __syncthreads();

    const int wt = tid & 63;
    const int hr = tid >> 6;
    const int w0 = wt * 4;

    float4 rr[CPG], prev[CPG];
    #pragma unroll
    for (int c = 0; c < CPG; c++) {
        rr[c]   = __ldcs(reinterpret_cast<const float4*>(
                      &ref[(size_t)((cbase + c)*Hh + h0 + hr)*Ww + w0]));
        prev[c] = *reinterpret_cast<const float4*>(&st[c][hr][52 + w0]);
    }

    float* vbase = vol + ((size_t)(b*Gg + g)*Dd*Hh + (size_t)(h0 + hr))*Ww + w0;

    #pragma unroll 2
    for (int d0 = 0; d0 < Dd; d0 += 4) {
        float4 A[CPG];
        #pragma unroll
        for (int c = 0; c < CPG; c++)
            A[c] = *reinterpret_cast<const float4*>(&st[c][hr][48 + w0 - d0]);
        #pragma unroll
        for (int k = 0; k < 4; k++) {
            float a0 = 0.f, a1 = 0.f, a2 = 0.f, a3 = 0.f;
            #pragma unroll
            for (int c = 0; c < CPG; c++) {
                float V[7] = { A[c].x, A[c].y, A[c].z, A[c].w,
                               prev[c].x, prev[c].y, prev[c].z };
                a0 += rr[c].x * V[3 - k];
                a1 += rr[c].y * V[4 - k];
                a2 += rr[c].z * V[5 - k];
                a3 += rr[c].w * V[6 - k];
            }
            float4 o = make_float4(a0*0.125f, a1*0.125f, a2*0.125f, a3*0.125f);
            __stcs(reinterpret_cast<float4*>(vbase + (size_t)(d0 + k)*HW), o);
        }
        #pragma unroll
        for (int c = 0; c < CPG; c++) prev[c] = A[c];
    }
}

// ---------------------------------------------------------------------------
// Kernel 3: fuse conv implicit GEMM via mma.sync.m16n8k16.f16 (fp32 acc).
// fbase selects the batch-n chunk: fid in [fbase, fbase+128).
// ---------------------------------------------------------------------------
#define SMF_B0  0
#define SMF_B1  18432
#define SMF_P0  36864
#define SMF_P1  53760
#define SMF_TOT 70656

__global__ void __launch_bounds__(256, 2) fuse_mma_kernel(float* __restrict__ out,
                                                          int fbase) {
    extern __shared__ __align__(16) char smem[];
    const uint32_t sb = smem_u32(smem);
    const int fid  = blockIdx.x + fbase;
    const int tid  = threadIdx.x;
    const int wid  = tid >> 5;
    const int lane = tid & 31;
    const int q    = lane & 3;
    const int e    = lane >> 2;
    const int w0   = (fid & 1) * 128;
    const int h    = ((fid >> 1) & 63) * 2;
    const int n    = fid >> 7;
    const int colb = w0 + 4;

    int offsA[9];
    #pragma unroll
    for (int s = 0; s < 9; s++) offsA[s] = (s/3)*132 + (s%3);
    int baseT[2];
    #pragma unroll
    for (int t = 0; t < 2; t++) {
        int p = wid*32 + t*16 + e;
        baseT[t] = (p >> 7)*132 + (p & 127);
    }
    const int qb0 = q*528, qb1 = (q+4)*528;
    const int sw  = q << 3;

    auto stage = [&](int blk, int j) {
        const uint32_t pdst = sb + (j ? SMF_P1 : SMF_P0);
        for (int u = tid; u < 1056; u += 256) {
            int cp = u / 132, rm = u % 132;
            int r = rm / 33, f = rm % 33;
            const uint32_t* src = g_mu
                + ((size_t)((n*MPAIR + blk*8 + cp)*MROWS + h + r))*MSTR + colb + f*4;
            cpasync16(pdst + (uint32_t)((cp*528 + r*132 + f*4)*4), src);
        }
        const uint32_t bdst = sb + (j ? SMF_B1 : SMF_B0);
        const uint32_t* fsrc = g_fwrh + (size_t)blk*72*64;
        for (int u = tid; u < 1152; u += 256)
            cpasync16(bdst + (uint32_t)(u*16), fsrc + u*4);
    };

    float acc[2][8][4];
    #pragma unroll
    for (int t = 0; t < 2; t++)
        #pragma unroll
        for (int nt = 0; nt < 8; nt++)
            #pragma unroll
            for (int r = 0; r < 4; r++) acc[t][nt][r] = 0.f;

    stage(0, 0);
    CP_COMMIT();

    for (int blk = 0; blk < 16; blk++) {
        const int j = blk & 1;
        if (blk < 15) { stage(blk + 1, j ^ 1); CP_COMMIT(); }
        if (blk < 15) CP_WAIT(1); else CP_WAIT(0);
        __syncthreads();

        const uint32_t* P32 = (const uint32_t*)(smem + (j ? SMF_P1 : SMF_P0));
        const uint32_t* B32 = (const uint32_t*)(smem + (j ? SMF_B1 : SMF_B0));

        #pragma unroll
        for (int s = 0; s < 9; s++) {
            uint32_t a[2][4];
            #pragma unroll
            for (int t = 0; t < 2; t++) {
                const uint32_t* A0 = P32 + qb0 + baseT[t] + offsA[s];
                const uint32_t* A1 = P32 + qb1 + baseT[t] + offsA[s];
                a[t][0] = A0[0]; a[t][1] = A0[8];
                a[t][2] = A1[0]; a[t][3] = A1[8];
            }
            const int row0 = (s*8 + q)*64, row1 = (s*8 + q + 4)*64;
            #pragma unroll
            for (int nt = 0; nt < 8; nt++) {
                const int col = (nt*8 + e) ^ sw;
                uint32_t b0 = B32[row0 + col];
                uint32_t b1 = B32[row1 + col];
                mma_f16(acc[0][nt], a[0], b0, b1);
                mma_f16(acc[1][nt], a[1], b0, b1);
            }
        }
        __syncthreads();
    }

    float* ob = out + (size_t)n*XC*HW;
    #pragma unroll
    for (int t = 0; t < 2; t++) {
        int p0 = wid*32 + t*16 + e;
        int p1 = p0 + 8;
        int i0 = (h + (p0 >> 7))*Ww + w0 + (p0 & 127);
        int i1 = (h + (p1 >> 7))*Ww + w0 + (p1 & 127);
        #pragma unroll
        for (int nt = 0; nt < 8; nt++) {
            int o = nt*8 + q*2;
            __stcs(&ob[(size_t)o*HW + i0],     fmaxf(acc[t][nt][0], 0.f));
            __stcs(&ob[(size_t)(o+1)*HW + i0], fmaxf(acc[t][nt][1], 0.f));
            __stcs(&ob[(size_t)o*HW + i1],     fmaxf(acc[t][nt][2], 0.f));
            __stcs(&ob[(size_t)(o+1)*HW + i1], fmaxf(acc[t][nt][3], 0.f));
        }
    }
}

// ---------------------------------------------------------------------------
// Kernel 2a: zero the halo of the half2 merged scratch
// ---------------------------------------------------------------------------
__global__ void __launch_bounds__(256) halo_zero_kernel() {
    const int img = blockIdx.x;           // Bn*MPAIR = 256
    const int tid = threadIdx.x;
    uint32_t* base = g_mu + (size_t)img*MPSZ;
    for (int q = tid; q < MSTR; q += 256) {
        base[q] = 0u;
        base[(size_t)129*MSTR + q] = 0u;
    }
    for (int i = tid; i < 1024; i += 256) {
        int row = 1 + (i >> 3);
        int c8  = i & 7;
        int col = (c8 < 5) ? c8 : (256 + c8);
        base[(size_t)row*MSTR + col] = 0u;
    }
}

// ---------------------------------------------------------------------------
// Kernel 2b: dynamic conv, channel-PAIR blocks, fp16 half2 output.
// Batch index n passed explicitly (pipelined per-n launches).
// ---------------------------------------------------------------------------
__global__ void __launch_bounds__(256) dynconv_kernel(const float* __restrict__ x,
                                                      const float* __restrict__ ker,
                                                      int n) {
    __shared__ __align__(16) float xs[2][14][272];
    const int tid = threadIdx.x;
    const int h0  = blockIdx.x * 4;
    const int cp  = blockIdx.y;           // 0..31
    const int c0  = cp*2;

    for (int i = tid; i < 2*14*16; i += 256) {
        int ch = i / 224, rm = i % 224;
        int row = rm >> 4, c16 = rm & 15;
        int col = (c16 < 8) ? c16 : (256 + c16);
        xs[ch][row][col] = 0.f;
    }
    for (int i = tid; i < 2*14*64; i += 256) {
        int ch = i / 896, rm = i % 896;
        int rr = rm >> 6, f = rm & 63;
        int gr = h0 - 5 + rr;
        float4 v = make_float4(0.f, 0.f, 0.f, 0.f);
        if ((unsigned)gr < (unsigned)Hh)
            v = __ldcs(reinterpret_cast<const float4*>(
                    x + (size_t)(n*XC + c0 + ch)*HW + (size_t)gr*Ww + f*4));
        *reinterpret_cast<float4*>(&xs[ch][rr][8 + f*4]) = v;
    }
    __syncthreads();

    const int w = tid;
    #pragma unroll
    for (int r = 0; r < 4; r++) {
        const int h = h0 + r;
        float res[2][4];
        #pragma unroll
        for (int ch = 0; ch < 2; ch++) {
            const float* kp = ker + ((size_t)(n*XC + c0 + ch)*9*Hh + h)*Ww + w;
            float a1 = 0.f, a3 = 0.f, a5 = 0.f;
            #pragma unroll
            for (int i = 0; i < 3; i++) {
                #pragma unroll
                for (int j = 0; j < 3; j++) {
                    const float kvt = __ldcs(&kp[(size_t)(i*3 + j)*HW]);
                    a1 += xs[ch][r + 4 + i  ][w + 7 + j  ] * kvt;
                    a3 += xs[ch][r + 2 + 3*i][w + 5 + 3*j] * kvt;
                    a5 += xs[ch][r + 5*i    ][w + 3 + 5*j] * kvt;
                }
            }
            res[ch][0] = xs[ch][r + 5][w + 8];
            res[ch][1] = a1; res[ch][2] = a3; res[ch][3] = a5;
        }
        uint32_t* mb = g_mu + ((size_t)((n*MPAIR + cp)*MROWS) + h + 1)*MSTR + w + 5;
        #pragma unroll
        for (int b = 0; b < 4; b++)
            mb[(size_t)b*32*MPSZ] = pack2h(res[0][b], res[1][b]);
    }
}

// ---------------------------------------------------------------------------
// Kernel 2c: pack fuse weights to swizzled half2 pairs [chunk][kp][o^sw]
// ---------------------------------------------------------------------------
__global__ void __launch_bounds__(256) prep_fw_kernel(const float* __restrict__ fw) {
    int gidx = blockIdx.x * 256 + threadIdx.x;      // 288*256 = 73728
    int o  = gidx & 63;
    int kp = (gidx >> 6) % 72;
    int ch = gidx / (72*64);
    int t  = kp >> 3, p = kp & 7;
    int c0 = ch*16 + p*2;
    float v0 = fw[(size_t)o*2304 + c0*9 + t];
    float v1 = fw[(size_t)o*2304 + (c0+1)*9 + t];
    int dcol = o ^ ((kp & 3) << 3);
    g_fwrh[(size_t)ch*72*64 + kp*64 + dcol] = pack2h(v0, v1);
}

// ---------------------------------------------------------------------------
// Launch graph (pipelined by batch n):
//   s2:   gwc ──────────────────────────────(evJoin)
//   s3:   halo, prep ──(evPre)
//   main: dc(n=0) ─(evD0)─ dc(n=1) ─(evD1)
//   s4:   wait(evD0,evPre) fuse(n=0) ── wait(evD1) fuse(n=1) ──(evF)
//   main: wait(evF), wait(evJoin)
// ---------------------------------------------------------------------------
extern "C" void kernel_launch(void* const* d_in, const int* in_sizes, int n_in,
                              void* d_out, int out_size) {
    const float* ref = (const float*)d_in[0];
    const float* tgt = (const float*)d_in[1];
    const float* x   = (const float*)d_in[2];
    const float* ker = (const float*)d_in[3];
    const float* fw  = (const float*)d_in[4];

    float* vol  = (float*)d_out;
    float* out2 = vol + (size_t)Bn*Gg*Dd*HW;

    static cudaStream_t s2 = nullptr, s3 = nullptr, s4 = nullptr;
    static cudaEvent_t evFork = nullptr, evPre = nullptr, evJoin = nullptr;
    static cudaEvent_t evD0 = nullptr, evD1 = nullptr, evF = nullptr;
    static bool attrSet = false;
    if (s2 == nullptr) {
        cudaStreamCreateWithFlags(&s2, cudaStreamNonBlocking);
        cudaStreamCreateWithFlags(&s3, cudaStreamNonBlocking);
        cudaStreamCreateWithFlags(&s4, cudaStreamNonBlocking);
        cudaEventCreateWithFlags(&evFork, cudaEventDisableTiming);
        cudaEventCreateWithFlags(&evPre,  cudaEventDisableTiming);
        cudaEventCreateWithFlags(&evJoin, cudaEventDisableTiming);
        cudaEventCreateWithFlags(&evD0,   cudaEventDisableTiming);
        cudaEventCreateWithFlags(&evD1,   cudaEventDisableTiming);
        cudaEventCreateWithFlags(&evF,    cudaEventDisableTiming);
    }
    if (!attrSet) {
        cudaFuncSetAttribute(fuse_mma_kernel,
                             cudaFuncAttributeMaxDynamicSharedMemorySize, SMF_TOT);
        attrSet = true;
    }

    // fork side branches
    cudaEventRecord(evFork, 0);
    cudaStreamWaitEvent(s2, evFork, 0);
    cudaStreamWaitEvent(s3, evFork, 0);
    cudaStreamWaitEvent(s4, evFork, 0);

    // s2: cost volume starts immediately, fills leftover bandwidth
    gwc_kernel<<<dim3(Hh/4, Gg, Bn), 256, 0, s2>>>(ref, tgt, vol);
    cudaEventRecord(evJoin, s2);

    // s3: tiny prep work for fuse
    halo_zero_kernel<<<Bn*MPAIR, 256, 0, s3>>>();
    prep_fw_kernel<<<288, 256, 0, s3>>>(fw);
    cudaEventRecord(evPre, s3);

    // main: dynconv per batch, pipelined
    dynconv_kernel<<<dim3(Hh/4, XC/2, 1), 256>>>(x, ker, 0);
    cudaEventRecord(evD0, 0);
    dynconv_kernel<<<dim3(Hh/4, XC/2, 1), 256>>>(x, ker, 1);
    cudaEventRecord(evD1, 0);

    // s4: fuse per batch, each gated only on its own dynconv chunk
    cudaStreamWaitEvent(s4, evD0, 0);
    cudaStreamWaitEvent(s4, evPre, 0);
    fuse_mma_kernel<<<128, 256, SMF_TOT, s4>>>(out2, 0);
    cudaStreamWaitEvent(s4, evD1, 0);
    fuse_mma_kernel<<<128, 256, SMF_TOT, s4>>>(out2, 128);
    cudaEventRecord(evF, s4);

    // join
    cudaStreamWaitEvent(0, evF, 0);
    cudaStreamWaitEvent(0, evJoin, 0);
}

// round 13
// speedup vs baseline: 1.1513x; 1.1513x over previous
#include <cuda_runtime.h>
#include <cuda_fp16.h>
#include <cstdint>

// Problem constants
#define Bn   2
#define Cc   320
#define Hh   128
#define Ww   256
#define Gg   40
#define CPG  8
#define Dd   48
#define XC   64
#define HW   (Hh*Ww)

// Merged scratch: half2 channel pairs. [n][mpair(128)][row(130)][col(264)] u32
#define MPAIR  128
#define MROWS  130
#define MSTR   264
#define MPSZ   (MROWS*MSTR)
#define MUTOT  ((size_t)Bn*MPAIR*MPSZ)

__device__ uint32_t g_mu[MUTOT];
__device__ uint32_t g_fwrh[16*72*64];   // packed half2 weights [chunk][kp(72)][o^sw(64)]

// ---------------------------------------------------------------------------
// helpers
// ---------------------------------------------------------------------------
__device__ __forceinline__ uint32_t pack2h(float a, float b) {
    __half2 h = __halves2half2(__float2half_rn(a), __float2half_rn(b));
    return *reinterpret_cast<uint32_t*>(&h);
}
__device__ __forceinline__ uint32_t smem_u32(const void* p) {
    uint32_t a;
    asm("{ .reg .u64 t; cvta.to.shared.u64 t, %1; cvt.u32.u64 %0, t; }" : "=r"(a) : "l"(p));
    return a;
}
__device__ __forceinline__ void cpasync16(uint32_t dst, const void* src) {
    asm volatile("cp.async.cg.shared.global [%0], [%1], 16;" :: "r"(dst), "l"(src) : "memory");
}
#define CP_COMMIT() asm volatile("cp.async.commit_group;" ::: "memory")
#define CP_WAIT(N)  asm volatile("cp.async.wait_group %0;" :: "n"(N) : "memory")

__device__ __forceinline__ void mma_f16(float* c, const uint32_t* a,
                                        uint32_t b0, uint32_t b1) {
    asm volatile("mma.sync.aligned.m16n8k16.row.col.f32.f16.f16.f32 "
        "{%0,%1,%2,%3}, {%4,%5,%6,%7}, {%8,%9}, {%0,%1,%2,%3};"
        : "+f"(c[0]), "+f"(c[1]), "+f"(c[2]), "+f"(c[3])
        : "r"(a[0]), "r"(a[1]), "r"(a[2]), "r"(a[3]), "r"(b0), "r"(b1));
}

// ---------------------------------------------------------------------------
// Kernel 1: groupwise-correlation cost volume (exact fp32) — register-lean.
// Per (c, d0): 7-value tgt window read as two LDS.128; 16 accumulators.
// Accumulation order (c = 0..7 into each acc) identical to prior versions.
// ---------------------------------------------------------------------------
__global__ void __launch_bounds__(256) gwc_kernel(const float* __restrict__ ref,
                                                  const float* __restrict__ tgt,
                                                  float* __restrict__ vol) {
    __shared__ __align__(16) float st[CPG][4][308];
    const int h0  = blockIdx.x * 4;
    const int g   = blockIdx.y;
    const int b   = blockIdx.z;
    const int tid = threadIdx.x;

    for (int q = tid; q < CPG*4*308; q += 256)
        (&st[0][0][0])[q] = 0.0f;
    __syncthreads();

    const int cbase = b*Cc + g*CPG;
    for (int q = tid; q < CPG*4*Ww; q += 256) {
        int w  = q & 255;
        int hr = (q >> 8) & 3;
        int c  = q >> 10;
        st[c][hr][51 + w] = __ldcs(&tgt[(size_t)((cbase + c)*Hh + h0 + hr)*Ww + w]);
    }
    __syncthreads();

    const int wt = tid & 63;
    const int hr = tid >> 6;
    const int w0 = wt * 4;

    float4 rr[CPG];
    #pragma unroll
    for (int c = 0; c < CPG; c++)
        rr[c] = __ldcs(reinterpret_cast<const float4*>(
                    &ref[(size_t)((cbase + c)*Hh + h0 + hr)*Ww + w0]));

    float* vbase = vol + ((size_t)(b*Gg + g)*Dd*Hh + (size_t)(h0 + hr))*Ww + w0;

    #pragma unroll 1
    for (int d0 = 0; d0 < Dd; d0 += 4) {
        float acc[4][4];
        #pragma unroll
        for (int k = 0; k < 4; k++)
            #pragma unroll
            for (int j = 0; j < 4; j++) acc[k][j] = 0.f;

        #pragma unroll
        for (int c = 0; c < CPG; c++) {
            // V[i] = tgt[w0 - d0 - 3 + i], i = 0..7 (V[7] unused)
            float4 Va = *reinterpret_cast<const float4*>(&st[c][hr][48 + w0 - d0]);
            float4 Vb = *reinterpret_cast<const float4*>(&st[c][hr][52 + w0 - d0]);
            float V[8] = { Va.x, Va.y, Va.z, Va.w, Vb.x, Vb.y, Vb.z, Vb.w };
            #pragma unroll
            for (int k = 0; k < 4; k++) {
                acc[k][0] += rr[c].x * V[3 - k];
                acc[k][1] += rr[c].y * V[4 - k];
                acc[k][2] += rr[c].z * V[5 - k];
                acc[k][3] += rr[c].w * V[6 - k];
            }
        }
        #pragma unroll
        for (int k = 0; k < 4; k++) {
            float4 o = make_float4(acc[k][0]*0.125f, acc[k][1]*0.125f,
                                   acc[k][2]*0.125f, acc[k][3]*0.125f);
            __stcs(reinterpret_cast<float4*>(vbase + (size_t)(d0 + k)*HW), o);
        }
    }
}

// ---------------------------------------------------------------------------
// Kernel 3: fuse conv implicit GEMM via mma.sync.m16n8k16.f16 (fp32 acc).
// v2: CTA covers N=32 outputs (ohalf = bx&1), M=256 px tile unchanged.
// Register-lean (acc 32/thread) so 2 fuse CTAs + 1 gwc CTA co-reside per SM.
// smem: B 2x9216, A 2x16896 = 52224 B.
// ---------------------------------------------------------------------------
#define SMF_B0  0
#define SMF_B1  9216
#define SMF_P0  18432
#define SMF_P1  35328
#define SMF_TOT 52224

__global__ void __launch_bounds__(256, 2) fuse_mma_kernel(float* __restrict__ out) {
    extern __shared__ __align__(16) char smem[];
    const uint32_t sb = smem_u32(smem);
    const int bx    = blockIdx.x;
    const int ohalf = bx & 1;
    const int fid   = bx >> 1;
    const int tid  = threadIdx.x;
    const int wid  = tid >> 5;
    const int lane = tid & 31;
    const int q    = lane & 3;
    const int e    = lane >> 2;
    const int w0   = (fid & 1) * 128;
    const int h    = ((fid >> 1) & 63) * 2;
    const int n    = fid >> 7;
    const int colb = w0 + 4;

    int offsA[9];
    #pragma unroll
    for (int s = 0; s < 9; s++) offsA[s] = (s/3)*132 + (s%3);
    int baseT[2];
    #pragma unroll
    for (int t = 0; t < 2; t++) {
        int p = wid*32 + t*16 + e;
        baseT[t] = (p >> 7)*132 + (p & 127);
    }
    const int qb0 = q*528, qb1 = (q+4)*528;
    const int sw  = q << 3;

    auto stage = [&](int blk, int j) {
        const uint32_t pdst = sb + (j ? SMF_P1 : SMF_P0);
        for (int u = tid; u < 1056; u += 256) {
            int cp = u / 132, rm = u % 132;
            int r = rm / 33, f = rm % 33;
            const uint32_t* src = g_mu
                + ((size_t)((n*MPAIR + blk*8 + cp)*MROWS + h + r))*MSTR + colb + f*4;
            cpasync16(pdst + (uint32_t)((cp*528 + r*132 + f*4)*4), src);
        }
        // B: 72 kp x 32 cols (this CTA's o-half) = 576 x 16B
        const uint32_t bdst = sb + (j ? SMF_B1 : SMF_B0);
        const uint32_t* fsrc = g_fwrh + (size_t)blk*72*64 + ohalf*32;
        for (int u = tid; u < 576; u += 256) {
            int k = u >> 3, g8 = u & 7;
            cpasync16(bdst + (uint32_t)((k*32 + g8*4)*4), fsrc + k*64 + g8*4);
        }
    };

    float acc[2][4][4];
    #pragma unroll
    for (int t = 0; t < 2; t++)
        #pragma unroll
        for (int nt = 0; nt < 4; nt++)
            #pragma unroll
            for (int r = 0; r < 4; r++) acc[t][nt][r] = 0.f;

    stage(0, 0);
    CP_COMMIT();

    for (int blk = 0; blk < 16; blk++) {
        const int j = blk & 1;
        if (blk < 15) { stage(blk + 1, j ^ 1); CP_COMMIT(); }
        if (blk < 15) CP_WAIT(1); else CP_WAIT(0);
        __syncthreads();

        const uint32_t* P32 = (const uint32_t*)(smem + (j ? SMF_P1 : SMF_P0));
        const uint32_t* B32 = (const uint32_t*)(smem + (j ? SMF_B1 : SMF_B0));

        #pragma unroll
        for (int s = 0; s < 9; s++) {
            uint32_t a[2][4];
            #pragma unroll
            for (int t = 0; t < 2; t++) {
                const uint32_t* A0 = P32 + qb0 + baseT[t] + offsA[s];
                const uint32_t* A1 = P32 + qb1 + baseT[t] + offsA[s];
                a[t][0] = A0[0]; a[t][1] = A0[8];
                a[t][2] = A1[0]; a[t][3] = A1[8];
            }
            const int row0 = (s*8 + q)*32, row1 = (s*8 + q + 4)*32;
            #pragma unroll
            for (int nt = 0; nt < 4; nt++) {
                const int col = (nt*8 + e) ^ sw;     // in [0,32)
                uint32_t b0 = B32[row0 + col];
                uint32_t b1 = B32[row1 + col];
                mma_f16(acc[0][nt], a[0], b0, b1);
                mma_f16(acc[1][nt], a[1], b0, b1);
            }
        }
        __syncthreads();
    }

    float* ob = out + (size_t)n*XC*HW;
    #pragma unroll
    for (int t = 0; t < 2; t++) {
        int p0 = wid*32 + t*16 + e;
        int p1 = p0 + 8;
        int i0 = (h + (p0 >> 7))*Ww + w0 + (p0 & 127);
        int i1 = (h + (p1 >> 7))*Ww + w0 + (p1 & 127);
        #pragma unroll
        for (int nt = 0; nt < 4; nt++) {
            int o = ohalf*32 + nt*8 + q*2;
            __stcs(&ob[(size_t)o*HW + i0],     fmaxf(acc[t][nt][0], 0.f));
            __stcs(&ob[(size_t)(o+1)*HW + i0], fmaxf(acc[t][nt][1], 0.f));
            __stcs(&ob[(size_t)o*HW + i1],     fmaxf(acc[t][nt][2], 0.f));
            __stcs(&ob[(size_t)(o+1)*HW + i1], fmaxf(acc[t][nt][3], 0.f));
        }
    }
}

// ---------------------------------------------------------------------------
// Kernel 2a: zero the halo of the half2 merged scratch
// ---------------------------------------------------------------------------
__global__ void __launch_bounds__(256) halo_zero_kernel() {
    const int img = blockIdx.x;           // Bn*MPAIR = 256
    const int tid = threadIdx.x;
    uint32_t* base = g_mu + (size_t)img*MPSZ;
    for (int q = tid; q < MSTR; q += 256) {
        base[q] = 0u;
        base[(size_t)129*MSTR + q] = 0u;
    }
    for (int i = tid; i < 1024; i += 256) {
        int row = 1 + (i >> 3);
        int c8  = i & 7;
        int col = (c8 < 5) ? c8 : (256 + c8);
        base[(size_t)row*MSTR + col] = 0u;
    }
}

// ---------------------------------------------------------------------------
// Kernel 2b: dynamic conv, channel-PAIR blocks, fp16 half2 output.
// ---------------------------------------------------------------------------
__global__ void __launch_bounds__(256) dynconv_kernel(const float* __restrict__ x,
                                                      const float* __restrict__ ker) {
    __shared__ __align__(16) float xs[2][14][272];
    const int tid = threadIdx.x;
    const int h0  = blockIdx.x * 4;
    const int cp  = blockIdx.y;           // 0..31
    const int n   = blockIdx.z;
    const int c0  = cp*2;

    for (int i = tid; i < 2*14*16; i += 256) {
        int ch = i / 224, rm = i % 224;
        int row = rm >> 4, c16 = rm & 15;
        int col = (c16 < 8) ? c16 : (256 + c16);
        xs[ch][row][col] = 0.f;
    }
    for (int i = tid; i < 2*14*64; i += 256) {
        int ch = i / 896, rm = i % 896;
        int rr = rm >> 6, f = rm & 63;
        int gr = h0 - 5 + rr;
        float4 v = make_float4(0.f, 0.f, 0.f, 0.f);
        if ((unsigned)gr < (unsigned)Hh)
            v = __ldcs(reinterpret_cast<const float4*>(
                    x + (size_t)(n*XC + c0 + ch)*HW + (size_t)gr*Ww + f*4));
        *reinterpret_cast<float4*>(&xs[ch][rr][8 + f*4]) = v;
    }
    __syncthreads();

    const int w = tid;
    #pragma unroll
    for (int r = 0; r < 4; r++) {
        const int h = h0 + r;
        float res[2][4];
        #pragma unroll
        for (int ch = 0; ch < 2; ch++) {
            const float* kp = ker + ((size_t)(n*XC + c0 + ch)*9*Hh + h)*Ww + w;
            float a1 = 0.f, a3 = 0.f, a5 = 0.f;
            #pragma unroll
            for (int i = 0; i < 3; i++) {
                #pragma unroll
                for (int j = 0; j < 3; j++) {
                    const float kvt = __ldcs(&kp[(size_t)(i*3 + j)*HW]);
                    a1 += xs[ch][r + 4 + i  ][w + 7 + j  ] * kvt;
                    a3 += xs[ch][r + 2 + 3*i][w + 5 + 3*j] * kvt;
                    a5 += xs[ch][r + 5*i    ][w + 3 + 5*j] * kvt;
                }
            }
            res[ch][0] = xs[ch][r + 5][w + 8];
            res[ch][1] = a1; res[ch][2] = a3; res[ch][3] = a5;
        }
        uint32_t* mb = g_mu + ((size_t)((n*MPAIR + cp)*MROWS) + h + 1)*MSTR + w + 5;
        #pragma unroll
        for (int b = 0; b < 4; b++)
            mb[(size_t)b*32*MPSZ] = pack2h(res[0][b], res[1][b]);
    }
}

// ---------------------------------------------------------------------------
// Kernel 2c: pack fuse weights to swizzled half2 pairs [chunk][kp][o^sw]
// ---------------------------------------------------------------------------
__global__ void __launch_bounds__(256) prep_fw_kernel(const float* __restrict__ fw) {
    int gidx = blockIdx.x * 256 + threadIdx.x;      // 288*256 = 73728
    int o  = gidx & 63;
    int kp = (gidx >> 6) % 72;
    int ch = gidx / (72*64);
    int t  = kp >> 3, p = kp & 7;
    int c0 = ch*16 + p*2;
    float v0 = fw[(size_t)o*2304 + c0*9 + t];
    float v1 = fw[(size_t)o*2304 + (c0+1)*9 + t];
    int dcol = o ^ ((kp & 3) << 3);
    g_fwrh[(size_t)ch*72*64 + kp*64 + dcol] = pack2h(v0, v1);
}

// ---------------------------------------------------------------------------
// Launch graph (R9 topology):
//   s2:   gwc (starts t=0) ──────────────(evJoin)
//   s3:   halo, prep ──(evPre)
//   main: dynconv ── wait(evPre) ── fuse ── wait(evJoin)
// ---------------------------------------------------------------------------
extern "C" void kernel_launch(void* const* d_in, const int* in_sizes, int n_in,
                              void* d_out, int out_size) {
    const float* ref = (const float*)d_in[0];
    const float* tgt = (const float*)d_in[1];
    const float* x   = (const float*)d_in[2];
    const float* ker = (const float*)d_in[3];
    const float* fw  = (const float*)d_in[4];

    float* vol  = (float*)d_out;
    float* out2 = vol + (size_t)Bn*Gg*Dd*HW;

    static cudaStream_t s2 = nullptr, s3 = nullptr;
    static cudaEvent_t evFork = nullptr, evPre = nullptr, evJoin = nullptr;
    static bool attrSet = false;
    if (s2 == nullptr) {
        cudaStreamCreateWithFlags(&s2, cudaStreamNonBlocking);
        cudaStreamCreateWithFlags(&s3, cudaStreamNonBlocking);
        cudaEventCreateWithFlags(&evFork, cudaEventDisableTiming);
        cudaEventCreateWithFlags(&evPre,  cudaEventDisableTiming);
        cudaEventCreateWithFlags(&evJoin, cudaEventDisableTiming);
    }
    if (!attrSet) {
        cudaFuncSetAttribute(fuse_mma_kernel,
                             cudaFuncAttributeMaxDynamicSharedMemorySize, SMF_TOT);
        attrSet = true;
    }

    // fork both side branches
    cudaEventRecord(evFork, 0);
    cudaStreamWaitEvent(s2, evFork, 0);
    cudaStreamWaitEvent(s3, evFork, 0);

    // s2: cost volume starts immediately
    gwc_kernel<<<dim3(Hh/4, Gg, Bn), 256, 0, s2>>>(ref, tgt, vol);
    cudaEventRecord(evJoin, s2);

    // s3: tiny prep work for fuse
    halo_zero_kernel<<<Bn*MPAIR, 256, 0, s3>>>();
    prep_fw_kernel<<<288, 256, 0, s3>>>(fw);
    cudaEventRecord(evPre, s3);

    // main: dynconv then fuse
    dynconv_kernel<<<dim3(Hh/4, XC/2, Bn), 256>>>(x, ker);
    cudaStreamWaitEvent(0, evPre, 0);
    fuse_mma_kernel<<<512, 256, SMF_TOT>>>(out2);

    // join
    cudaStreamWaitEvent(0, evJoin, 0);
}

// round 14
// speedup vs baseline: 1.2896x; 1.1201x over previous
#include <cuda_runtime.h>
#include <cuda_fp16.h>
#include <cstdint>

// Problem constants
#define Bn   2
#define Cc   320
#define Hh   128
#define Ww   256
#define Gg   40
#define CPG  8
#define Dd   48
#define XC   64
#define HW   (Hh*Ww)

// Merged scratch: half2 channel pairs. [n][mpair(128)][row(130)][col(264)] u32
#define MPAIR  128
#define MROWS  130
#define MSTR   264
#define MPSZ   (MROWS*MSTR)
#define MUTOT  ((size_t)Bn*MPAIR*MPSZ)

__device__ uint32_t g_mu[MUTOT];
__device__ uint32_t g_fwrh[16*72*64];   // packed half2 weights [chunk][kp(72)][o^sw(64)]

// ---------------------------------------------------------------------------
// helpers
// ---------------------------------------------------------------------------
__device__ __forceinline__ uint32_t pack2h(float a, float b) {
    __half2 h = __halves2half2(__float2half_rn(a), __float2half_rn(b));
    return *reinterpret_cast<uint32_t*>(&h);
}
__device__ __forceinline__ uint32_t smem_u32(const void* p) {
    uint32_t a;
    asm("{ .reg .u64 t; cvta.to.shared.u64 t, %1; cvt.u32.u64 %0, t; }" : "=r"(a) : "l"(p));
    return a;
}
__device__ __forceinline__ void cpasync16(uint32_t dst, const void* src) {
    asm volatile("cp.async.cg.shared.global [%0], [%1], 16;" :: "r"(dst), "l"(src) : "memory");
}
#define CP_COMMIT() asm volatile("cp.async.commit_group;" ::: "memory")
#define CP_WAIT(N)  asm volatile("cp.async.wait_group %0;" :: "n"(N) : "memory")

__device__ __forceinline__ void mma_f16(float* c, const uint32_t* a,
                                        uint32_t b0, uint32_t b1) {
    asm volatile("mma.sync.aligned.m16n8k16.row.col.f32.f16.f16.f32 "
        "{%0,%1,%2,%3}, {%4,%5,%6,%7}, {%8,%9}, {%0,%1,%2,%3};"
        : "+f"(c[0]), "+f"(c[1]), "+f"(c[2]), "+f"(c[3])
        : "r"(a[0]), "r"(a[1]), "r"(a[2]), "r"(a[3]), "r"(b0), "r"(b1));
}

// ---------------------------------------------------------------------------
// Kernel 1: groupwise-correlation cost volume (exact fp32).
// 128-thread CTAs (64 wt x 2 h-rows), register-lean inner loop — small
// enough (regs+smem) to co-reside with fuse CTAs and fill idle DRAM slots.
// Accumulation order per output identical to all prior versions.
// ---------------------------------------------------------------------------
__global__ void __launch_bounds__(128) gwc_kernel(const float* __restrict__ ref,
                                                  const float* __restrict__ tgt,
                                                  float* __restrict__ vol) {
    __shared__ __align__(16) float st[CPG][2][308];
    const int h0  = blockIdx.x * 2;
    const int g   = blockIdx.y;
    const int b   = blockIdx.z;
    const int tid = threadIdx.x;

    for (int q = tid; q < CPG*2*308; q += 128)
        (&st[0][0][0])[q] = 0.0f;
    __syncthreads();

    const int cbase = b*Cc + g*CPG;
    for (int q = tid; q < CPG*2*Ww; q += 128) {
        int w  = q & 255;
        int hr = (q >> 8) & 1;
        int c  = q >> 9;
        st[c][hr][51 + w] = __ldcs(&tgt[(size_t)((cbase + c)*Hh + h0 + hr)*Ww + w]);
    }
    __syncthreads();

    const int wt = tid & 63;
    const int hr = tid >> 6;           // 0..1
    const int w0 = wt * 4;

    float4 rr[CPG];
    #pragma unroll
    for (int c = 0; c < CPG; c++)
        rr[c] = __ldcs(reinterpret_cast<const float4*>(
                    &ref[(size_t)((cbase + c)*Hh + h0 + hr)*Ww + w0]));

    float* vbase = vol + ((size_t)(b*Gg + g)*Dd*Hh + (size_t)(h0 + hr))*Ww + w0;

    #pragma unroll 1
    for (int d0 = 0; d0 < Dd; d0 += 4) {
        float acc[4][4];
        #pragma unroll
        for (int k = 0; k < 4; k++)
            #pragma unroll
            for (int j = 0; j < 4; j++) acc[k][j] = 0.f;

        #pragma unroll
        for (int c = 0; c < CPG; c++) {
            // V[i] = tgt[w0 - d0 - 3 + i]
            float4 Va = *reinterpret_cast<const float4*>(&st[c][hr][48 + w0 - d0]);
            float4 Vb = *reinterpret_cast<const float4*>(&st[c][hr][52 + w0 - d0]);
            float V[8] = { Va.x, Va.y, Va.z, Va.w, Vb.x, Vb.y, Vb.z, Vb.w };
            #pragma unroll
            for (int k = 0; k < 4; k++) {
                acc[k][0] += rr[c].x * V[3 - k];
                acc[k][1] += rr[c].y * V[4 - k];
                acc[k][2] += rr[c].z * V[5 - k];
                acc[k][3] += rr[c].w * V[6 - k];
            }
        }
        #pragma unroll
        for (int k = 0; k < 4; k++) {
            float4 o = make_float4(acc[k][0]*0.125f, acc[k][1]*0.125f,
                                   acc[k][2]*0.125f, acc[k][3]*0.125f);
            __stcs(reinterpret_cast<float4*>(vbase + (size_t)(d0 + k)*HW), o);
        }
    }
}

// ---------------------------------------------------------------------------
// Kernel 3: fuse conv implicit GEMM via mma.sync.m16n8k16.f16 (fp32 acc).
// R9-exact: M=256 px x N=64 outs per CTA, grid 256 (~1 wave at 2 CTA/SM).
// ---------------------------------------------------------------------------
#define SMF_B0  0
#define SMF_B1  18432
#define SMF_P0  36864
#define SMF_P1  53760
#define SMF_TOT 70656

__global__ void __launch_bounds__(256, 2) fuse_mma_kernel(float* __restrict__ out) {
    extern __shared__ __align__(16) char smem[];
    const uint32_t sb = smem_u32(smem);
    const int fid  = blockIdx.x;
    const int tid  = threadIdx.x;
    const int wid  = tid >> 5;
    const int lane = tid & 31;
    const int q    = lane & 3;
    const int e    = lane >> 2;
    const int w0   = (fid & 1) * 128;
    const int h    = ((fid >> 1) & 63) * 2;
    const int n    = fid >> 7;
    const int colb = w0 + 4;

    int offsA[9];
    #pragma unroll
    for (int s = 0; s < 9; s++) offsA[s] = (s/3)*132 + (s%3);
    int baseT[2];
    #pragma unroll
    for (int t = 0; t < 2; t++) {
        int p = wid*32 + t*16 + e;
        baseT[t] = (p >> 7)*132 + (p & 127);
    }
    const int qb0 = q*528, qb1 = (q+4)*528;
    const int sw  = q << 3;

    auto stage = [&](int blk, int j) {
        const uint32_t pdst = sb + (j ? SMF_P1 : SMF_P0);
        for (int u = tid; u < 1056; u += 256) {
            int cp = u / 132, rm = u % 132;
            int r = rm / 33, f = rm % 33;
            const uint32_t* src = g_mu
                + ((size_t)((n*MPAIR + blk*8 + cp)*MROWS + h + r))*MSTR + colb + f*4;
            cpasync16(pdst + (uint32_t)((cp*528 + r*132 + f*4)*4), src);
        }
        const uint32_t bdst = sb + (j ? SMF_B1 : SMF_B0);
        const uint32_t* fsrc = g_fwrh + (size_t)blk*72*64;
        for (int u = tid; u < 1152; u += 256)
            cpasync16(bdst + (uint32_t)(u*16), fsrc + u*4);
    };

    float acc[2][8][4];
    #pragma unroll
    for (int t = 0; t < 2; t++)
        #pragma unroll
        for (int nt = 0; nt < 8; nt++)
            #pragma unroll
            for (int r = 0; r < 4; r++) acc[t][nt][r] = 0.f;

    stage(0, 0);
    CP_COMMIT();

    for (int blk = 0; blk < 16; blk++) {
        const int j = blk & 1;
        if (blk < 15) { stage(blk + 1, j ^ 1); CP_COMMIT(); }
        if (blk < 15) CP_WAIT(1); else CP_WAIT(0);
        __syncthreads();

        const uint32_t* P32 = (const uint32_t*)(smem + (j ? SMF_P1 : SMF_P0));
        const uint32_t* B32 = (const uint32_t*)(smem + (j ? SMF_B1 : SMF_B0));

        #pragma unroll
        for (int s = 0; s < 9; s++) {
            uint32_t a[2][4];
            #pragma unroll
            for (int t = 0; t < 2; t++) {
                const uint32_t* A0 = P32 + qb0 + baseT[t] + offsA[s];
                const uint32_t* A1 = P32 + qb1 + baseT[t] + offsA[s];
                a[t][0] = A0[0]; a[t][1] = A0[8];
                a[t][2] = A1[0]; a[t][3] = A1[8];
            }
            const int row0 = (s*8 + q)*64, row1 = (s*8 + q + 4)*64;
            #pragma unroll
            for (int nt = 0; nt < 8; nt++) {
                const int col = (nt*8 + e) ^ sw;
                uint32_t b0 = B32[row0 + col];
                uint32_t b1 = B32[row1 + col];
                mma_f16(acc[0][nt], a[0], b0, b1);
                mma_f16(acc[1][nt], a[1], b0, b1);
            }
        }
        __syncthreads();
    }

    float* ob = out + (size_t)n*XC*HW;
    #pragma unroll
    for (int t = 0; t < 2; t++) {
        int p0 = wid*32 + t*16 + e;
        int p1 = p0 + 8;
        int i0 = (h + (p0 >> 7))*Ww + w0 + (p0 & 127);
        int i1 = (h + (p1 >> 7))*Ww + w0 + (p1 & 127);
        #pragma unroll
        for (int nt = 0; nt < 8; nt++) {
            int o = nt*8 + q*2;
            __stcs(&ob[(size_t)o*HW + i0],     fmaxf(acc[t][nt][0], 0.f));
            __stcs(&ob[(size_t)(o+1)*HW + i0], fmaxf(acc[t][nt][1], 0.f));
            __stcs(&ob[(size_t)o*HW + i1],     fmaxf(acc[t][nt][2], 0.f));
            __stcs(&ob[(size_t)(o+1)*HW + i1], fmaxf(acc[t][nt][3], 0.f));
        }
    }
}

// ---------------------------------------------------------------------------
// Kernel 2a: zero the halo of the half2 merged scratch
// ---------------------------------------------------------------------------
__global__ void __launch_bounds__(256) halo_zero_kernel() {
    const int img = blockIdx.x;           // Bn*MPAIR = 256
    const int tid = threadIdx.x;
    uint32_t* base = g_mu + (size_t)img*MPSZ;
    for (int q = tid; q < MSTR; q += 256) {
        base[q] = 0u;
        base[(size_t)129*MSTR + q] = 0u;
    }
    for (int i = tid; i < 1024; i += 256) {
        int row = 1 + (i >> 3);
        int c8  = i & 7;
        int col = (c8 < 5) ? c8 : (256 + c8);
        base[(size_t)row*MSTR + col] = 0u;
    }
}

// ---------------------------------------------------------------------------
// Kernel 2b: dynamic conv, channel-PAIR blocks, fp16 half2 output.
// ---------------------------------------------------------------------------
__global__ void __launch_bounds__(256) dynconv_kernel(const float* __restrict__ x,
                                                      const float* __restrict__ ker) {
    __shared__ __align__(16) float xs[2][14][272];
    const int tid = threadIdx.x;
    const int h0  = blockIdx.x * 4;
    const int cp  = blockIdx.y;           // 0..31
    const int n   = blockIdx.z;
    const int c0  = cp*2;

    for (int i = tid; i < 2*14*16; i += 256) {
        int ch = i / 224, rm = i % 224;
        int row = rm >> 4, c16 = rm & 15;
        int col = (c16 < 8) ? c16 : (256 + c16);
        xs[ch][row][col] = 0.f;
    }
    for (int i = tid; i < 2*14*64; i += 256) {
        int ch = i / 896, rm = i % 896;
        int rr = rm >> 6, f = rm & 63;
        int gr = h0 - 5 + rr;
        float4 v = make_float4(0.f, 0.f, 0.f, 0.f);
        if ((unsigned)gr < (unsigned)Hh)
            v = __ldcs(reinterpret_cast<const float4*>(
                    x + (size_t)(n*XC + c0 + ch)*HW + (size_t)gr*Ww + f*4));
        *reinterpret_cast<float4*>(&xs[ch][rr][8 + f*4]) = v;
    }
    __syncthreads();

    const int w = tid;
    #pragma unroll
    for (int r = 0; r < 4; r++) {
        const int h = h0 + r;
        float res[2][4];
        #pragma unroll
        for (int ch = 0; ch < 2; ch++) {
            const float* kp = ker + ((size_t)(n*XC + c0 + ch)*9*Hh + h)*Ww + w;
            float a1 = 0.f, a3 = 0.f, a5 = 0.f;
            #pragma unroll
            for (int i = 0; i < 3; i++) {
                #pragma unroll
                for (int j = 0; j < 3; j++) {
                    const float kvt = __ldcs(&kp[(size_t)(i*3 + j)*HW]);
                    a1 += xs[ch][r + 4 + i  ][w + 7 + j  ] * kvt;
                    a3 += xs[ch][r + 2 + 3*i][w + 5 + 3*j] * kvt;
                    a5 += xs[ch][r + 5*i    ][w + 3 + 5*j] * kvt;
                }
            }
            res[ch][0] = xs[ch][r + 5][w + 8];
            res[ch][1] = a1; res[ch][2] = a3; res[ch][3] = a5;
        }
        uint32_t* mb = g_mu + ((size_t)((n*MPAIR + cp)*MROWS) + h + 1)*MSTR + w + 5;
        #pragma unroll
        for (int b = 0; b < 4; b++)
            mb[(size_t)b*32*MPSZ] = pack2h(res[0][b], res[1][b]);
    }
}

// ---------------------------------------------------------------------------
// Kernel 2c: pack fuse weights to swizzled half2 pairs [chunk][kp][o^sw]
// ---------------------------------------------------------------------------
__global__ void __launch_bounds__(256) prep_fw_kernel(const float* __restrict__ fw) {
    int gidx = blockIdx.x * 256 + threadIdx.x;      // 288*256 = 73728
    int o  = gidx & 63;
    int kp = (gidx >> 6) % 72;
    int ch = gidx / (72*64);
    int t  = kp >> 3, p = kp & 7;
    int c0 = ch*16 + p*2;
    float v0 = fw[(size_t)o*2304 + c0*9 + t];
    float v1 = fw[(size_t)o*2304 + (c0+1)*9 + t];
    int dcol = o ^ ((kp & 3) << 3);
    g_fwrh[(size_t)ch*72*64 + kp*64 + dcol] = pack2h(v0, v1);
}

// ---------------------------------------------------------------------------
// Launch graph (R9 topology):
//   s2:   gwc (starts t=0) ──────────────(evJoin)
//   s3:   halo, prep ──(evPre)
//   main: dynconv ── wait(evPre) ── fuse ── wait(evJoin)
// ---------------------------------------------------------------------------
extern "C" void kernel_launch(void* const* d_in, const int* in_sizes, int n_in,
                              void* d_out, int out_size) {
    const float* ref = (const float*)d_in[0];
    const float* tgt = (const float*)d_in[1];
    const float* x   = (const float*)d_in[2];
    const float* ker = (const float*)d_in[3];
    const float* fw  = (const float*)d_in[4];

    float* vol  = (float*)d_out;
    float* out2 = vol + (size_t)Bn*Gg*Dd*HW;

    static cudaStream_t s2 = nullptr, s3 = nullptr;
    static cudaEvent_t evFork = nullptr, evPre = nullptr, evJoin = nullptr;
    static bool attrSet = false;
    if (s2 == nullptr) {
        cudaStreamCreateWithFlags(&s2, cudaStreamNonBlocking);
        cudaStreamCreateWithFlags(&s3, cudaStreamNonBlocking);
        cudaEventCreateWithFlags(&evFork, cudaEventDisableTiming);
        cudaEventCreateWithFlags(&evPre,  cudaEventDisableTiming);
        cudaEventCreateWithFlags(&evJoin, cudaEventDisableTiming);
    }
    if (!attrSet) {
        cudaFuncSetAttribute(fuse_mma_kernel,
                             cudaFuncAttributeMaxDynamicSharedMemorySize, SMF_TOT);
        attrSet = true;
    }

    // fork both side branches
    cudaEventRecord(evFork, 0);
    cudaStreamWaitEvent(s2, evFork, 0);
    cudaStreamWaitEvent(s3, evFork, 0);

    // s2: cost volume starts immediately (128-thr CTAs, gap-filling shape)
    gwc_kernel<<<dim3(Hh/2, Gg, Bn), 128, 0, s2>>>(ref, tgt, vol);
    cudaEventRecord(evJoin, s2);

    // s3: tiny prep work for fuse
    halo_zero_kernel<<<Bn*MPAIR, 256, 0, s3>>>();
    prep_fw_kernel<<<288, 256, 0, s3>>>(fw);
    cudaEventRecord(evPre, s3);

    // main: dynconv then fuse
    dynconv_kernel<<<dim3(Hh/4, XC/2, Bn), 256>>>(x, ker);
    cudaStreamWaitEvent(0, evPre, 0);
    fuse_mma_kernel<<<256, 256, SMF_TOT>>>(out2);

    // join
    cudaStreamWaitEvent(0, evJoin, 0);
}